// round 12
// baseline (speedup 1.0000x reference)
#include <cuda_runtime.h>
#include <cuda_bf16.h>

// Champion form (rounds 10/11): HBM-bound at ~86% DRAM busy / 6.85 TB/s.
// Tested & rejected: 2x unroll (occupancy loss), persistent grid (-5%),
// .cs/.wt/.cg hints (-1..-4%), TMA bulk stores (-2%), BLOCK=512 (tie).
#define BLOCK 128

__global__ __launch_bounds__(BLOCK)
void gaussian_pre_kernel(
    const float*  __restrict__ scaling_raw,  // [N,3]
    const float4* __restrict__ rotation,     // [N,4]
    const float*  __restrict__ opacity_raw,  // [N]
    const float4* __restrict__ features4,    // [N,16,3] as float4, row stride 12
    float* __restrict__ cov3d,               // [N,9]
    float4* __restrict__ cov2d4,             // [N,4]
    float* __restrict__ color,               // [N,3]
    float* __restrict__ opacity,             // [N]
    int N)
{
    __shared__ float s_cov[BLOCK * 9];
    __shared__ float s_col[BLOCK * 3];

    const int tid  = threadIdx.x;
    const int base = blockIdx.x * BLOCK;
    const int i    = base + tid;
    const int cnt  = min(BLOCK, N - base);

    if (i < N) {
        // ---- issue all global loads back-to-back (one MLP batch) ----
        const float4 f   = features4[i * 12];       // first 16B of 192B row
        const float4 q   = rotation[i];
        const float  sr0 = scaling_raw[3 * i + 0];
        const float  sr1 = scaling_raw[3 * i + 1];
        const float  sr2 = scaling_raw[3 * i + 2];
        const float  o   = opacity_raw[i];

        // quaternion -> rotation matrix (normalized)
        float inv = rsqrtf(q.x * q.x + q.y * q.y + q.z * q.z + q.w * q.w);
        float w = q.x * inv, x = q.y * inv, y = q.z * inv, z = q.w * inv;

        float R00 = 1.f - 2.f * (y * y + z * z);
        float R01 = 2.f * (x * y - w * z);
        float R02 = 2.f * (x * z + w * y);
        float R10 = 2.f * (x * y + w * z);
        float R11 = 1.f - 2.f * (x * x + z * z);
        float R12 = 2.f * (y * z - w * x);
        float R20 = 2.f * (x * z - w * y);
        float R21 = 2.f * (y * z + w * x);
        float R22 = 1.f - 2.f * (x * x + y * y);

        // sigma^2 = exp(2*scaling)
        float s0 = __expf(2.f * sr0);
        float s1 = __expf(2.f * sr1);
        float s2 = __expf(2.f * sr2);

        // cov2d: trace(R D R^T) = trace(D) = s0+s1+s2 (R orthonormal)
        float var = (s0 + s1 + s2) * (1.0f / 3.0f);
        cov2d4[i]  = make_float4(var, 0.f, 0.f, var);
        opacity[i] = 1.0f / (1.0f + __expf(-o));

        float c00 = R00 * R00 * s0 + R01 * R01 * s1 + R02 * R02 * s2;
        float c01 = R00 * R10 * s0 + R01 * R11 * s1 + R02 * R12 * s2;
        float c02 = R00 * R20 * s0 + R01 * R21 * s1 + R02 * R22 * s2;
        float c11 = R10 * R10 * s0 + R11 * R11 * s1 + R12 * R12 * s2;
        float c12 = R10 * R20 * s0 + R11 * R21 * s1 + R12 * R22 * s2;
        float c22 = R20 * R20 * s0 + R21 * R21 * s1 + R22 * R22 * s2;

        float* sc = &s_cov[tid * 9];   // stride 9: bank-conflict-free
        sc[0] = c00; sc[1] = c01; sc[2] = c02;
        sc[3] = c01; sc[4] = c11; sc[5] = c12;
        sc[6] = c02; sc[7] = c12; sc[8] = c22;

        s_col[tid * 3 + 0] = f.x;
        s_col[tid * 3 + 1] = f.y;
        s_col[tid * 3 + 2] = f.z;
    }
    __syncthreads();

    // ---- coalesced vectorized flush (default cache policy) ----
    if (cnt == BLOCK) {
        const float4* s4 = reinterpret_cast<const float4*>(s_cov);
        float4* d4 = reinterpret_cast<float4*>(cov3d + base * 9);
        d4[tid]         = s4[tid];
        d4[tid + BLOCK] = s4[tid + BLOCK];
        if (tid < (BLOCK * 9) / 4 - 2 * BLOCK)            // remaining 32
            d4[tid + 2 * BLOCK] = s4[tid + 2 * BLOCK];

        const float4* c4 = reinterpret_cast<const float4*>(s_col);
        float4* e4 = reinterpret_cast<float4*>(color + base * 3);
        if (tid < (BLOCK * 3) / 4)                        // 96
            e4[tid] = c4[tid];
    } else {
        const int n9 = cnt * 9;
        float* dst9 = cov3d + base * 9;
        for (int j = tid; j < n9; j += BLOCK) dst9[j] = s_cov[j];
        const int n3 = cnt * 3;
        float* dst3 = color + base * 3;
        for (int j = tid; j < n3; j += BLOCK) dst3[j] = s_col[j];
    }
}

extern "C" void kernel_launch(void* const* d_in, const int* in_sizes, int n_in,
                              void* d_out, int out_size) {
    // inputs: 0 xyz, 1 scaling_raw[N,3], 2 rotation[N,4], 3 opacity_raw[N,1],
    //         4 features[N,16,3], 5 viewmatrix, 6 projmatrix
    const float*  scaling  = (const float*) d_in[1];
    const float4* rotation = (const float4*)d_in[2];
    const float*  opac_raw = (const float*) d_in[3];
    const float4* features = (const float4*)d_in[4];

    const int N = in_sizes[3];

    float* out    = (float*)d_out;
    float*  cov3d = out;                                  // 9N
    float4* cov2d = (float4*)(out + (long long)9 * N);    // 4N
    float*  color = out + (long long)13 * N;              // 3N
    float*  opac  = out + (long long)16 * N;              // N

    int grid = (N + BLOCK - 1) / BLOCK;
    gaussian_pre_kernel<<<grid, BLOCK>>>(scaling, rotation, opac_raw, features,
                                         cov3d, cov2d, color, opac, N);
}

// round 13
// speedup vs baseline: 1.0014x; 1.0014x over previous
#include <cuda_runtime.h>
#include <cuda_bf16.h>

// FINAL champion (rounds 10-12): HBM-bound at ~86.7% DRAM busy / 6.87 TB/s.
// Tested & rejected across the session: 2x unroll (occupancy loss, -5%),
// persistent grid (-5%), .cs/.wt/.cg cache hints (-1..-4%), TMA bulk
// stores (-3%), BLOCK=512 (tie), per-warp staging (tie).
#define BLOCK 128

__global__ __launch_bounds__(BLOCK)
void gaussian_pre_kernel(
    const float*  __restrict__ scaling_raw,  // [N,3]
    const float4* __restrict__ rotation,     // [N,4]
    const float*  __restrict__ opacity_raw,  // [N]
    const float4* __restrict__ features4,    // [N,16,3] as float4, row stride 12
    float* __restrict__ cov3d,               // [N,9]
    float4* __restrict__ cov2d4,             // [N,4]
    float* __restrict__ color,               // [N,3]
    float* __restrict__ opacity,             // [N]
    int N)
{
    __shared__ float s_cov[BLOCK * 9];
    __shared__ float s_col[BLOCK * 3];

    const int tid  = threadIdx.x;
    const int base = blockIdx.x * BLOCK;
    const int i    = base + tid;
    const int cnt  = min(BLOCK, N - base);

    if (i < N) {
        // ---- issue all global loads back-to-back (one MLP batch) ----
        const float4 f   = features4[i * 12];       // first 16B of 192B row
        const float4 q   = rotation[i];
        const float  sr0 = scaling_raw[3 * i + 0];
        const float  sr1 = scaling_raw[3 * i + 1];
        const float  sr2 = scaling_raw[3 * i + 2];
        const float  o   = opacity_raw[i];

        // quaternion -> rotation matrix (normalized)
        float inv = rsqrtf(q.x * q.x + q.y * q.y + q.z * q.z + q.w * q.w);
        float w = q.x * inv, x = q.y * inv, y = q.z * inv, z = q.w * inv;

        float R00 = 1.f - 2.f * (y * y + z * z);
        float R01 = 2.f * (x * y - w * z);
        float R02 = 2.f * (x * z + w * y);
        float R10 = 2.f * (x * y + w * z);
        float R11 = 1.f - 2.f * (x * x + z * z);
        float R12 = 2.f * (y * z - w * x);
        float R20 = 2.f * (x * z - w * y);
        float R21 = 2.f * (y * z + w * x);
        float R22 = 1.f - 2.f * (x * x + y * y);

        // sigma^2 = exp(2*scaling)
        float s0 = __expf(2.f * sr0);
        float s1 = __expf(2.f * sr1);
        float s2 = __expf(2.f * sr2);

        // cov2d: trace(R D R^T) = trace(D) = s0+s1+s2 (R orthonormal)
        float var = (s0 + s1 + s2) * (1.0f / 3.0f);
        cov2d4[i]  = make_float4(var, 0.f, 0.f, var);
        opacity[i] = 1.0f / (1.0f + __expf(-o));

        float c00 = R00 * R00 * s0 + R01 * R01 * s1 + R02 * R02 * s2;
        float c01 = R00 * R10 * s0 + R01 * R11 * s1 + R02 * R12 * s2;
        float c02 = R00 * R20 * s0 + R01 * R21 * s1 + R02 * R22 * s2;
        float c11 = R10 * R10 * s0 + R11 * R11 * s1 + R12 * R12 * s2;
        float c12 = R10 * R20 * s0 + R11 * R21 * s1 + R12 * R22 * s2;
        float c22 = R20 * R20 * s0 + R21 * R21 * s1 + R22 * R22 * s2;

        float* sc = &s_cov[tid * 9];   // stride 9: bank-conflict-free
        sc[0] = c00; sc[1] = c01; sc[2] = c02;
        sc[3] = c01; sc[4] = c11; sc[5] = c12;
        sc[6] = c02; sc[7] = c12; sc[8] = c22;

        s_col[tid * 3 + 0] = f.x;
        s_col[tid * 3 + 1] = f.y;
        s_col[tid * 3 + 2] = f.z;
    }
    __syncthreads();

    // ---- coalesced vectorized flush (default cache policy) ----
    if (cnt == BLOCK) {
        const float4* s4 = reinterpret_cast<const float4*>(s_cov);
        float4* d4 = reinterpret_cast<float4*>(cov3d + base * 9);
        d4[tid]         = s4[tid];
        d4[tid + BLOCK] = s4[tid + BLOCK];
        if (tid < (BLOCK * 9) / 4 - 2 * BLOCK)            // remaining 32
            d4[tid + 2 * BLOCK] = s4[tid + 2 * BLOCK];

        const float4* c4 = reinterpret_cast<const float4*>(s_col);
        float4* e4 = reinterpret_cast<float4*>(color + base * 3);
        if (tid < (BLOCK * 3) / 4)                        // 96
            e4[tid] = c4[tid];
    } else {
        const int n9 = cnt * 9;
        float* dst9 = cov3d + base * 9;
        for (int j = tid; j < n9; j += BLOCK) dst9[j] = s_cov[j];
        const int n3 = cnt * 3;
        float* dst3 = color + base * 3;
        for (int j = tid; j < n3; j += BLOCK) dst3[j] = s_col[j];
    }
}

extern "C" void kernel_launch(void* const* d_in, const int* in_sizes, int n_in,
                              void* d_out, int out_size) {
    // inputs: 0 xyz, 1 scaling_raw[N,3], 2 rotation[N,4], 3 opacity_raw[N,1],
    //         4 features[N,16,3], 5 viewmatrix, 6 projmatrix
    const float*  scaling  = (const float*) d_in[1];
    const float4* rotation = (const float4*)d_in[2];
    const float*  opac_raw = (const float*) d_in[3];
    const float4* features = (const float4*)d_in[4];

    const int N = in_sizes[3];

    float* out    = (float*)d_out;
    float*  cov3d = out;                                  // 9N
    float4* cov2d = (float4*)(out + (long long)9 * N);    // 4N
    float*  color = out + (long long)13 * N;              // 3N
    float*  opac  = out + (long long)16 * N;              // N

    int grid = (N + BLOCK - 1) / BLOCK;
    gaussian_pre_kernel<<<grid, BLOCK>>>(scaling, rotation, opac_raw, features,
                                         cov3d, cov2d, color, opac, N);
}